// round 2
// baseline (speedup 1.0000x reference)
#include <cuda_runtime.h>

#define N_USERS 100000
#define M_ITEMS 50000
#define NTOT    150000
#define EMBED   64
#define BATCH   8192
#define NNZ     2400000

// Scratch: static device globals (no allocation allowed in kernel_launch).
// 3 x 150000 x 64 floats = 115 MB total.
__device__ float g_A[(size_t)NTOT * EMBED];
__device__ float g_B[(size_t)NTOT * EMBED];
__device__ float g_S[(size_t)NTOT * EMBED];

__device__ __forceinline__ float* pickAB(int sel) { return sel ? g_B : g_A; }

static const size_t N4 = (size_t)NTOT * EMBED / 4;  // float4 count per table

// Init: A = S = concat(embed_user_0, embed_item_0); zero the reg_loss slot.
__global__ void k_init(const float* __restrict__ eu, const float* __restrict__ ei,
                       float* __restrict__ out) {
    size_t i = (size_t)blockIdx.x * blockDim.x + threadIdx.x;
    const size_t total = (size_t)NTOT * EMBED / 4;
    if (i >= total) return;
    const size_t userQ = (size_t)N_USERS * EMBED / 4;
    float4 v;
    if (i < userQ) v = reinterpret_cast<const float4*>(eu)[i];
    else           v = reinterpret_cast<const float4*>(ei)[i - userQ];
    reinterpret_cast<float4*>(g_A)[i] = v;
    reinterpret_cast<float4*>(g_S)[i] = v;
    if (i == 0) out[2 * BATCH] = 0.0f;
}

// Zero one ping-pong buffer (sel: 0 -> A, 1 -> B).
__global__ void k_zero(int sel) {
    size_t i = (size_t)blockIdx.x * blockDim.x + threadIdx.x;
    const size_t total = (size_t)NTOT * EMBED / 4;
    if (i >= total) return;
    reinterpret_cast<float4*>(pickAB(sel))[i] = make_float4(0.f, 0.f, 0.f, 0.f);
}

// Edge scatter: out[src] += val * in[dst]. 16 threads per edge, float4 each.
// inSel=0: A -> B ; inSel=1: B -> A.
__global__ void k_scatter(const int* __restrict__ src, const int* __restrict__ dst,
                          const float* __restrict__ vals, int inSel) {
    unsigned int t = blockIdx.x * blockDim.x + threadIdx.x;
    unsigned int e = t >> 4;
    if (e >= NNZ) return;
    unsigned int c = t & 15u;
    const float* __restrict__ in = pickAB(inSel);
    float* __restrict__ outp = pickAB(inSel ^ 1);
    int s = src[e];
    int d = dst[e];
    float v = __ldg(vals + e);
    float4 a = *reinterpret_cast<const float4*>(in + (size_t)d * EMBED + c * 4);
    float* p = outp + (size_t)s * EMBED + c * 4;
    asm volatile("red.global.add.v4.f32 [%0], {%1, %2, %3, %4};"
                 :: "l"(p), "f"(a.x * v), "f"(a.y * v), "f"(a.z * v), "f"(a.w * v)
                 : "memory");
}

// S += (sel ? B : A)
__global__ void k_accum(int sel) {
    size_t i = (size_t)blockIdx.x * blockDim.x + threadIdx.x;
    const size_t total = (size_t)NTOT * EMBED / 4;
    if (i >= total) return;
    float4 v = reinterpret_cast<const float4*>(pickAB(sel))[i];
    float4 s = reinterpret_cast<float4*>(g_S)[i];
    s.x += v.x; s.y += v.y; s.z += v.z; s.w += v.w;
    reinterpret_cast<float4*>(g_S)[i] = s;
}

// Predictions: light_out = S/4; pred = dot(light_out[u], light_out[item]).
// One warp per batch element; each lane owns a float2 (64 floats / 32 lanes).
__global__ void k_pred(const int* __restrict__ user, const int* __restrict__ item_i,
                       const int* __restrict__ item_j, float* __restrict__ out) {
    unsigned int gw = (blockIdx.x * blockDim.x + threadIdx.x) >> 5;
    unsigned int lane = threadIdx.x & 31u;
    if (gw >= BATCH) return;
    int u  = user[gw];
    int ii = item_i[gw] + N_USERS;
    int jj = item_j[gw] + N_USERS;
    float2 ue = reinterpret_cast<const float2*>(g_S + (size_t)u  * EMBED)[lane];
    float2 ie = reinterpret_cast<const float2*>(g_S + (size_t)ii * EMBED)[lane];
    float2 je = reinterpret_cast<const float2*>(g_S + (size_t)jj * EMBED)[lane];
    float di = ue.x * ie.x + ue.y * ie.y;
    float dj = ue.x * je.x + ue.y * je.y;
    #pragma unroll
    for (int o = 16; o; o >>= 1) {
        di += __shfl_xor_sync(0xffffffffu, di, o);
        dj += __shfl_xor_sync(0xffffffffu, dj, o);
    }
    if (lane == 0) {
        out[gw]         = di * 0.0625f;   // (1/4)*(1/4)
        out[BATCH + gw] = dj * 0.0625f;
    }
}

// reg_loss = 0.5 * (sum u0^2 + sum i0^2 + sum j0^2) / BATCH, accumulated
// via one atomicAdd per 256-thread block into out[2*BATCH] (zeroed by k_init).
__global__ void k_reg(const int* __restrict__ user, const int* __restrict__ item_i,
                      const int* __restrict__ item_j,
                      const float* __restrict__ eu, const float* __restrict__ ei,
                      float* __restrict__ out) {
    unsigned int gw = (blockIdx.x * blockDim.x + threadIdx.x) >> 5;
    unsigned int lane = threadIdx.x & 31u;
    float s = 0.0f;
    if (gw < 3 * BATCH) {
        unsigned int which = gw / BATCH;
        unsigned int b = gw % BATCH;
        const float* row;
        if (which == 0)      row = eu + (size_t)user[b]   * EMBED;
        else if (which == 1) row = ei + (size_t)item_i[b] * EMBED;
        else                 row = ei + (size_t)item_j[b] * EMBED;
        float2 v = reinterpret_cast<const float2*>(row)[lane];
        s = v.x * v.x + v.y * v.y;
    }
    #pragma unroll
    for (int o = 16; o; o >>= 1) s += __shfl_xor_sync(0xffffffffu, s, o);
    __shared__ float sh[8];
    unsigned int w = threadIdx.x >> 5;
    if (lane == 0) sh[w] = s;
    __syncthreads();
    if (threadIdx.x == 0) {
        float t = 0.0f;
        #pragma unroll
        for (int k = 0; k < 8; k++) t += sh[k];
        atomicAdd(out + 2 * BATCH, t * (0.5f / (float)BATCH));
    }
}

extern "C" void kernel_launch(void* const* d_in, const int* in_sizes, int n_in,
                              void* d_out, int out_size) {
    const int*   user   = (const int*)d_in[0];
    const int*   item_i = (const int*)d_in[1];
    const int*   item_j = (const int*)d_in[2];
    // d_in[3] timestamp, d_in[4] split_idx: unused by the reference output
    const int*   esrc   = (const int*)d_in[5];
    const int*   edst   = (const int*)d_in[6];
    const float* evals  = (const float*)d_in[7];
    const float* eu     = (const float*)d_in[8];
    const float* ei     = (const float*)d_in[9];
    float* out = (float*)d_out;

    const int gb = (int)((N4 + 255) / 256);                    // table-wide float4 kernels
    const int sb = (int)(((long long)NNZ * 16 + 255) / 256);   // scatter: 16 thr/edge

    k_init<<<gb, 256>>>(eu, ei, out);

    // 3 propagation layers, ping-pong A<->B, accumulate into S.
    for (int l = 0; l < 3; l++) {
        int inSel  = l & 1;        // 0: read A, write B ; 1: read B, write A
        int outSel = inSel ^ 1;
        k_zero<<<gb, 256>>>(outSel);
        k_scatter<<<sb, 256>>>(esrc, edst, evals, inSel);
        k_accum<<<gb, 256>>>(outSel);
    }

    k_pred<<<(BATCH * 32) / 256, 256>>>(user, item_i, item_j, out);
    k_reg<<<(3 * BATCH * 32) / 256, 256>>>(user, item_i, item_j, eu, ei, out);
}